// round 4
// baseline (speedup 1.0000x reference)
#include <cuda_runtime.h>
#include <cstdint>
#include <cstddef>

// ---------------------------------------------------------------------------
// metaLinear: y[t,o] = sum_j x2[t,j] * ( sum_i x1[t,i]*W[j*64+o,i] + bvec[j*64+o] )
// tokens = 16384, IN1=256, IN2=64, OUT=64.
//
// Dual-path: the harness compiles with virtual arch compute_103 (no 'a'), where
// tcgen05 is illegal. Fallback = mma.sync m16n8k8 tf32 (sm_80+). If an
// sm_103a pass exists (__CUDA_ARCH_FEAT_SM103_ALL), use tcgen05 instead.
// Both paths: per-CTA 128-token tile, 64 j-chunks of N=64, K=256; W prepacked
// into a device global and streamed via cp.async.bulk + mbarrier ring.
// ---------------------------------------------------------------------------

#if defined(__CUDA_ARCH_FEAT_SM103_ALL) || defined(__CUDA_ARCH_FEAT_SM100_ALL)
#define HAS_TCGEN05 1
#else
#define HAS_TCGEN05 0
#endif

#define TOK_TILE 128
#define NCHUNK   64
#define KCHUNK   8
#define NST      6

#define OFF_TMEM 0
#define OFF_MBAR 16
#define OFF_A    1024                       // 128 KB (x1 tile, path-specific layout)
#define OFF_B    (OFF_A + 131072)           // 132096: NST x 8192 B ring
#define OFF_X2   (OFF_B + NST * 8192)       // 181248: x2 (path-specific layout)
#define OFF_BV   (OFF_X2 + 33280)           // 214528: 4096 floats bias
#define SMEM_TOTAL (OFF_BV + 16384)         // 230912 bytes

__device__ __align__(1024) static float g_Wpk[4096 * 256];   // prepacked W (4 MB)

// ---------------------------- common helpers -------------------------------

static __device__ __forceinline__ uint32_t smem_u32(const void* p) {
    uint32_t a;
    asm("{ .reg .u64 t; cvta.to.shared.u64 t, %1; cvt.u32.u64 %0, t; }"
        : "=r"(a) : "l"(p));
    return a;
}
static __device__ __forceinline__ void mbar_init(uint32_t m, uint32_t cnt) {
    asm volatile("mbarrier.init.shared.b64 [%0], %1;" :: "r"(m), "r"(cnt) : "memory");
}
static __device__ __forceinline__ void mbar_arrive(uint32_t m) {
    asm volatile("mbarrier.arrive.shared.b64 _, [%0];" :: "r"(m) : "memory");
}
static __device__ __forceinline__ void mbar_expect_tx(uint32_t m, uint32_t bytes) {
    asm volatile("mbarrier.arrive.expect_tx.shared.b64 _, [%0], %1;"
                 :: "r"(m), "r"(bytes) : "memory");
}
static __device__ __forceinline__ void mbar_wait(uint32_t m, uint32_t parity) {
    asm volatile(
        "{\n\t"
        ".reg .pred P;\n\t"
        "LAB_%=:\n\t"
        "mbarrier.try_wait.parity.acquire.cta.shared::cta.b64 P, [%0], %1, 0x989680;\n\t"
        "@P bra DONE_%=;\n\t"
        "bra LAB_%=;\n\t"
        "DONE_%=:\n\t"
        "}"
        :: "r"(m), "r"(parity) : "memory");
}
static __device__ __forceinline__ void bulk_g2s(uint32_t dst, const void* src,
                                                uint32_t bytes, uint32_t mbar) {
    asm volatile(
        "cp.async.bulk.shared::cluster.global.mbarrier::complete_tx::bytes "
        "[%0], [%1], %2, [%3];"
        :: "r"(dst), "l"(src), "r"(bytes), "r"(mbar) : "memory");
}
static __device__ __forceinline__ uint32_t f2tf32(float v) {
    uint32_t u;
    asm("cvt.rna.tf32.f32 %0, %1;" : "=r"(u) : "f"(v));
    return u;
}

#if HAS_TCGEN05
// ---------------------------- tcgen05 helpers ------------------------------
#define IDESC_TF32 ((1u << 4) | (2u << 7) | (2u << 10) | (8u << 17) | (8u << 24))
#define DESC_BASE 0x4000404000010000ULL

static __device__ __forceinline__ uint64_t make_desc(uint32_t addr) {
    return DESC_BASE | (uint64_t)((addr >> 4) & 0x3FFF);
}
static __device__ __forceinline__ void mma_tc_tf32(uint32_t d, uint64_t ad, uint64_t bd,
                                                   uint32_t idesc, uint32_t en) {
    asm volatile(
        "{\n\t"
        ".reg .pred p;\n\t"
        "setp.ne.u32 p, %5, 0;\n\t"
        "tcgen05.mma.cta_group::1.kind::tf32 [%0], %1, %2, %3, {%4, %4, %4, %4}, p;\n\t"
        "}"
        :: "r"(d), "l"(ad), "l"(bd), "r"(idesc), "r"(0u), "r"(en) : "memory");
}
static __device__ __forceinline__ void tc_commit(uint32_t mbar) {
    asm volatile(
        "tcgen05.commit.cta_group::1.mbarrier::arrive::one.shared::cluster.b64 [%0];"
        :: "r"(mbar) : "memory");
}
static __device__ __forceinline__ void ldtm32(uint32_t* r, uint32_t tmem_addr) {
    asm volatile(
        "tcgen05.ld.sync.aligned.32x32b.x32.b32 "
        "{%0, %1, %2, %3, %4, %5, %6, %7, "
        " %8, %9, %10, %11, %12, %13, %14, %15, "
        " %16, %17, %18, %19, %20, %21, %22, %23, "
        " %24, %25, %26, %27, %28, %29, %30, %31}, [%32];"
        : "=r"(r[0]),  "=r"(r[1]),  "=r"(r[2]),  "=r"(r[3]),
          "=r"(r[4]),  "=r"(r[5]),  "=r"(r[6]),  "=r"(r[7]),
          "=r"(r[8]),  "=r"(r[9]),  "=r"(r[10]), "=r"(r[11]),
          "=r"(r[12]), "=r"(r[13]), "=r"(r[14]), "=r"(r[15]),
          "=r"(r[16]), "=r"(r[17]), "=r"(r[18]), "=r"(r[19]),
          "=r"(r[20]), "=r"(r[21]), "=r"(r[22]), "=r"(r[23]),
          "=r"(r[24]), "=r"(r[25]), "=r"(r[26]), "=r"(r[27]),
          "=r"(r[28]), "=r"(r[29]), "=r"(r[30]), "=r"(r[31])
        : "r"(tmem_addr));
}
#else
// ---------------------------- mma.sync helper ------------------------------
static __device__ __forceinline__ void mma_frag_tf32(float* d, const uint32_t* a,
                                                     uint32_t b0, uint32_t b1) {
    asm volatile(
        "mma.sync.aligned.m16n8k8.row.col.f32.tf32.tf32.f32 "
        "{%0,%1,%2,%3}, {%4,%5,%6,%7}, {%8,%9}, {%0,%1,%2,%3};"
        : "+f"(d[0]), "+f"(d[1]), "+f"(d[2]), "+f"(d[3])
        : "r"(a[0]), "r"(a[1]), "r"(a[2]), "r"(a[3]), "r"(b0), "r"(b1));
}
#endif

// ------------------------ kernel 1: prepack W ------------------------------
// W (4096 x 256 fp32) -> per-chunk tiled, tf32-rounded, layout per path.

__global__ void prepack_w_kernel(const float* __restrict__ W) {
    int idx = blockIdx.x * 256 + threadIdx.x;   // 0 .. 1048575
    uint32_t u = f2tf32(W[idx]);
#if HAS_TCGEN05
    // [jc][kc] 64x32 blocks, SW128-swizzled 128B rows (SS-mma B operand)
    int r  = idx >> 8;
    int cc = idx & 255;
    int jc = r >> 6, rl = r & 63;
    int kc = cc >> 5, cl = cc & 31;
    uint32_t off = (uint32_t)(rl * 128 + cl * 4);
    off ^= (off >> 3) & 0x70;
    *reinterpret_cast<uint32_t*>(
        reinterpret_cast<char*>(g_Wpk) + (size_t)(jc * KCHUNK + kc) * 8192 + off) = u;
#else
    // fragment-major for mma.sync m16n8k8 (B operand, col-major k8 x n8):
    // [chunk(64)][stage(8)][kstep(4)][ntile_pair(4)][lane(32)][4 vals]
    int r  = idx >> 8;
    int cc = idx & 255;
    int chunk = r >> 6, o = r & 63;
    int ntile = o >> 3, c8o = o & 7;
    int kg = cc >> 3, stage = kg >> 2, kst = kg & 3, r8 = cc & 7;
    int lane = c8o * 4 + (r8 & 3);
    int reg  = r8 >> 2;
    int np   = ntile >> 1;
    int val  = ((ntile & 1) << 1) | reg;
    size_t off = ((((size_t)(chunk * 8 + stage) * 4 + kst) * 4 + np) * 32 + lane) * 16
                 + (size_t)val * 4;
    *reinterpret_cast<uint32_t*>(reinterpret_cast<char*>(g_Wpk) + off) = u;
#endif
}

// --------------------------- main kernel -----------------------------------
// 128 CTAs x 192 threads.
// tcgen05 path: warps 0-3 epilogue, warp 4 MMA issue, warp 5 producer.
// fallback path: warps 0-3 compute mma.sync, warp 4 producer, warp 5 idle.

__global__ void __launch_bounds__(192, 1)
meta_main_kernel(const float* __restrict__ x1, const float* __restrict__ x2,
                 const float* __restrict__ bvec, float* __restrict__ out) {
    extern __shared__ __align__(1024) char smem[];
    const uint32_t sb = smem_u32(smem);
    const int tid  = threadIdx.x;
    const int wid  = tid >> 5;
    const int lane = tid & 31;
    const int cta  = blockIdx.x;
    const uint32_t MB = sb + OFF_MBAR;

#if HAS_TCGEN05
    // ======================= tcgen05 path ==================================
    if (tid == 0) {
        for (int s = 0; s < NST; s++) { mbar_init(MB + s * 8, 1); mbar_init(MB + 48 + s * 8, 1); }
        mbar_init(MB + 96, 1);  mbar_init(MB + 104, 1);
        mbar_init(MB + 112, 1); mbar_init(MB + 120, 1);
    }
    if (wid == 4) {
        asm volatile("tcgen05.alloc.cta_group::1.sync.aligned.shared::cta.b32 [%0], %1;"
                     :: "r"(sb + OFF_TMEM), "r"(128u) : "memory");
        asm volatile("tcgen05.relinquish_alloc_permit.cta_group::1.sync.aligned;" ::: "memory");
    }

    const float* x1p = x1 + (size_t)cta * (TOK_TILE * 256);
    for (int i = tid; i < TOK_TILE * 256; i += 192) {
        int t = i >> 8, c = i & 255;
        int kc = c >> 5, cl = c & 31;
        uint32_t off = (uint32_t)((t << 7) | (cl << 2));
        off ^= (off >> 3) & 0x70;
        *reinterpret_cast<uint32_t*>(smem + OFF_A + kc * 16384 + off) = f2tf32(x1p[i]);
    }
    const float* x2p = x2 + (size_t)cta * (TOK_TILE * 64);
    float* sx2 = reinterpret_cast<float*>(smem + OFF_X2);
    for (int i = tid; i < TOK_TILE * 64; i += 192) {
        int t = i >> 6, c = i & 63;
        sx2[t * 65 + c] = x2p[i];
    }
    float* sbv = reinterpret_cast<float*>(smem + OFF_BV);
    for (int i = tid; i < 4096; i += 192) sbv[i] = bvec[i];

    asm volatile("fence.proxy.async.shared::cta;" ::: "memory");
    __syncthreads();

    uint32_t tmem;
    asm volatile("ld.shared.b32 %0, [%1];" : "=r"(tmem) : "r"(sb + OFF_TMEM));

    if (wid == 5 && lane == 0) {
        const char* src = reinterpret_cast<const char*>(g_Wpk);
        for (int t = 0; t < NCHUNK * KCHUNK; t++) {
            int s = t % NST, u = t / NST;
            if (u > 0) mbar_wait(MB + 48 + s * 8, (u + 1) & 1);
            mbar_expect_tx(MB + s * 8, 8192);
            bulk_g2s(sb + OFF_B + s * 8192, src + (size_t)t * 8192, 8192, MB + s * 8);
        }
    } else if (wid == 4 && lane == 0) {
        for (int c = 0; c < NCHUNK; c++) {
            int buf = c & 1;
            if (c >= 2) {
                int v = c >> 1;
                mbar_wait(MB + 112 + buf * 8, (v - 1) & 1);
                asm volatile("tcgen05.fence::after_thread_sync;" ::: "memory");
            }
            uint32_t d = tmem + buf * 64;
            for (int kc = 0; kc < KCHUNK; kc++) {
                int t = c * KCHUNK + kc;
                int s = t % NST;
                mbar_wait(MB + s * 8, (t / NST) & 1);
                uint64_t ad = make_desc(sb + OFF_A + kc * 16384);
                uint64_t bd = make_desc(sb + OFF_B + s * 8192);
#pragma unroll
                for (int ks = 0; ks < 4; ks++)
                    mma_tc_tf32(d, ad + ks * 2, bd + ks * 2, IDESC_TF32,
                                (uint32_t)((kc | ks) != 0));
                tc_commit(MB + 48 + s * 8);
            }
            tc_commit(MB + 96 + buf * 8);
        }
    } else if (wid < 4) {
        float acc[64];
#pragma unroll
        for (int o = 0; o < 64; o++) acc[o] = 0.0f;
        const float* myx2 = sx2 + tid * 65;

        for (int c = 0; c < NCHUNK; c++) {
            int buf = c & 1;
            int v = c >> 1;
            mbar_wait(MB + 96 + buf * 8, v & 1);
            asm volatile("tcgen05.fence::after_thread_sync;" ::: "memory");
            uint32_t w0[32], w1[32];
            ldtm32(w0, tmem + buf * 64);
            ldtm32(w1, tmem + buf * 64 + 32);
            asm volatile("tcgen05.wait::ld.sync.aligned;" ::: "memory");
            asm volatile("tcgen05.fence::before_thread_sync;" ::: "memory");
            asm volatile("bar.sync 1, 128;" ::: "memory");
            if (tid == 0) mbar_arrive(MB + 112 + buf * 8);

            float xv = myx2[c];
            const float* bvc = sbv + c * 64;
#pragma unroll
            for (int o = 0; o < 32; o++)
                acc[o] = fmaf(xv, __uint_as_float(w0[o]) + bvc[o], acc[o]);
#pragma unroll
            for (int o = 0; o < 32; o++)
                acc[32 + o] = fmaf(xv, __uint_as_float(w1[o]) + bvc[32 + o], acc[32 + o]);
        }

        float4* op = reinterpret_cast<float4*>(out + ((size_t)cta * TOK_TILE + tid) * 64);
#pragma unroll
        for (int o = 0; o < 16; o++)
            op[o] = make_float4(acc[4 * o], acc[4 * o + 1], acc[4 * o + 2], acc[4 * o + 3]);
    }

    __syncthreads();
    if (wid == 4) {
        asm volatile("tcgen05.dealloc.cta_group::1.sync.aligned.b32 %0, %1;"
                     :: "r"(tmem), "r"(128u));
    }
#else
    // ======================= mma.sync fallback path ========================
    // mbar layout: full[s]=MB+8s, empty[s]=MB+64+8s (empty count=4: one per warp)
    if (tid == 0) {
        for (int s = 0; s < NST; s++) { mbar_init(MB + s * 8, 1); mbar_init(MB + 64 + s * 8, 4); }
    }

    // ---- prologue: pack x1 fragment-major (A operand m16n8k8 row-major) ----
    // layout: [warp(4)][kstep(32)][mtile(2)][lane(32)][4 vals] = 128 KB
    const float* x1p = x1 + (size_t)cta * (TOK_TILE * 256);
    for (int i = tid; i < TOK_TILE * 256; i += 192) {
        int t = i >> 8, c = i & 255;
        int w = t >> 5, mt = (t >> 4) & 1, r16 = t & 15;
        int kg = c >> 3, c8 = c & 7;
        int ln  = (r16 & 7) * 4 + (c8 & 3);
        int reg = ((r16 >> 3) & 1) | (((c8 >> 2) & 1) << 1);
        uint32_t off = (uint32_t)(((((w * 32 + kg) * 2 + mt) * 32 + ln) << 4) + (reg << 2));
        *reinterpret_cast<uint32_t*>(smem + OFF_A + off) = f2tf32(x1p[i]);
    }
    // x2 transposed: [chunk(64)][token(128)]
    const float* x2p = x2 + (size_t)cta * (TOK_TILE * 64);
    float* sx2 = reinterpret_cast<float*>(smem + OFF_X2);
    for (int i = tid; i < TOK_TILE * 64; i += 192) {
        int t = i >> 6, j = i & 63;
        sx2[j * 128 + t] = x2p[i];
    }
    float* sbv = reinterpret_cast<float*>(smem + OFF_BV);
    for (int i = tid; i < 4096; i += 192) sbv[i] = bvec[i];
    __syncthreads();

    if (wid == 4) {
        if (lane == 0) {
            const char* src = reinterpret_cast<const char*>(g_Wpk);
            for (int t = 0; t < NCHUNK * 8; t++) {
                int s = t % NST, u = t / NST;
                if (u > 0) mbar_wait(MB + 64 + s * 8, (u + 1) & 1);
                mbar_expect_tx(MB + s * 8, 8192);
                bulk_g2s(sb + OFF_B + s * 8192, src + (size_t)t * 8192, 8192, MB + s * 8);
            }
        }
    } else if (wid < 4) {
        float acc[2][8][4];
#pragma unroll
        for (int m = 0; m < 2; m++)
#pragma unroll
            for (int n = 0; n < 8; n++)
#pragma unroll
                for (int v = 0; v < 4; v++) acc[m][n][v] = 0.0f;

        const char* aW = smem + OFF_A + wid * 32768 + lane * 16;
        const int r = lane >> 2, q = lane & 3;

        for (int c = 0; c < NCHUNK; c++) {
            float C[2][8][4];
#pragma unroll
            for (int m = 0; m < 2; m++)
#pragma unroll
                for (int n = 0; n < 8; n++)
#pragma unroll
                    for (int v = 0; v < 4; v++) C[m][n][v] = 0.0f;

            for (int st = 0; st < 8; st++) {
                int t = c * 8 + st;
                int s = t % NST;
                mbar_wait(MB + s * 8, (t / NST) & 1);
                const char* bS = smem + OFF_B + s * 8192 + lane * 16;
#pragma unroll
                for (int k = 0; k < 4; k++) {
                    int kg = st * 4 + k;
                    uint4 a0 = *reinterpret_cast<const uint4*>(aW + kg * 1024);
                    uint4 a1 = *reinterpret_cast<const uint4*>(aW + kg * 1024 + 512);
                    uint4 bq0 = *reinterpret_cast<const uint4*>(bS + k * 2048);
                    uint4 bq1 = *reinterpret_cast<const uint4*>(bS + k * 2048 + 512);
                    uint4 bq2 = *reinterpret_cast<const uint4*>(bS + k * 2048 + 1024);
                    uint4 bq3 = *reinterpret_cast<const uint4*>(bS + k * 2048 + 1536);
                    const uint32_t* A0 = reinterpret_cast<const uint32_t*>(&a0);
                    const uint32_t* A1 = reinterpret_cast<const uint32_t*>(&a1);
                    mma_frag_tf32(C[0][0], A0, bq0.x, bq0.y);
                    mma_frag_tf32(C[0][1], A0, bq0.z, bq0.w);
                    mma_frag_tf32(C[0][2], A0, bq1.x, bq1.y);
                    mma_frag_tf32(C[0][3], A0, bq1.z, bq1.w);
                    mma_frag_tf32(C[0][4], A0, bq2.x, bq2.y);
                    mma_frag_tf32(C[0][5], A0, bq2.z, bq2.w);
                    mma_frag_tf32(C[0][6], A0, bq3.x, bq3.y);
                    mma_frag_tf32(C[0][7], A0, bq3.z, bq3.w);
                    mma_frag_tf32(C[1][0], A1, bq0.x, bq0.y);
                    mma_frag_tf32(C[1][1], A1, bq0.z, bq0.w);
                    mma_frag_tf32(C[1][2], A1, bq1.x, bq1.y);
                    mma_frag_tf32(C[1][3], A1, bq1.z, bq1.w);
                    mma_frag_tf32(C[1][4], A1, bq2.x, bq2.y);
                    mma_frag_tf32(C[1][5], A1, bq2.z, bq2.w);
                    mma_frag_tf32(C[1][6], A1, bq3.x, bq3.y);
                    mma_frag_tf32(C[1][7], A1, bq3.z, bq3.w);
                }
                __syncwarp();
                if (lane == 0) mbar_arrive(MB + 64 + s * 8);
            }

            // fold chunk into acc: acc += x2[t,c] * (C + bias)
            const float* xrow = sx2 + c * 128 + wid * 32;
            float xv00 = xrow[r];
            float xv01 = xrow[r + 8];
            float xv10 = xrow[r + 16];
            float xv11 = xrow[r + 24];
            const float* bvc = sbv + c * 64;
#pragma unroll
            for (int n = 0; n < 8; n++) {
                float bb0 = bvc[n * 8 + q * 2];
                float bb1 = bvc[n * 8 + q * 2 + 1];
                acc[0][n][0] = fmaf(xv00, C[0][n][0] + bb0, acc[0][n][0]);
                acc[0][n][1] = fmaf(xv00, C[0][n][1] + bb1, acc[0][n][1]);
                acc[0][n][2] = fmaf(xv01, C[0][n][2] + bb0, acc[0][n][2]);
                acc[0][n][3] = fmaf(xv01, C[0][n][3] + bb1, acc[0][n][3]);
                acc[1][n][0] = fmaf(xv10, C[1][n][0] + bb0, acc[1][n][0]);
                acc[1][n][1] = fmaf(xv10, C[1][n][1] + bb1, acc[1][n][1]);
                acc[1][n][2] = fmaf(xv11, C[1][n][2] + bb0, acc[1][n][2]);
                acc[1][n][3] = fmaf(xv11, C[1][n][3] + bb1, acc[1][n][3]);
            }
        }

        // store: rows (wid*32 + m*16 + {r, r+8}), cols (n*8 + q*2 + {0,1})
        int trow = cta * TOK_TILE + wid * 32 + r;
#pragma unroll
        for (int m = 0; m < 2; m++) {
#pragma unroll
            for (int n = 0; n < 8; n++) {
                float2 v0 = make_float2(acc[m][n][0], acc[m][n][1]);
                float2 v1 = make_float2(acc[m][n][2], acc[m][n][3]);
                *reinterpret_cast<float2*>(out + (size_t)(trow + m * 16) * 64 + n * 8 + q * 2) = v0;
                *reinterpret_cast<float2*>(out + (size_t)(trow + m * 16 + 8) * 64 + n * 8 + q * 2) = v1;
            }
        }
    }
    // warp 5 idle in fallback
#endif
}

// ------------------------------ launcher -----------------------------------

extern "C" void kernel_launch(void* const* d_in, const int* in_sizes, int n_in,
                              void* d_out, int out_size) {
    const float* x1 = (const float*)d_in[0];   // (4,4096,256)
    const float* x2 = (const float*)d_in[1];   // (4,4096,64)
    const float* W  = (const float*)d_in[2];   // (4096,256)
    const float* bv = (const float*)d_in[3];   // (4096,)
    float* out = (float*)d_out;                // (4,4096,64)

    cudaFuncSetAttribute(meta_main_kernel,
                         cudaFuncAttributeMaxDynamicSharedMemorySize, SMEM_TOTAL);

    prepack_w_kernel<<<4096, 256>>>(W);
    meta_main_kernel<<<128, 192, SMEM_TOTAL>>>(x1, x2, bv, out);
}